// round 1
// baseline (speedup 1.0000x reference)
#include <cuda_runtime.h>
#include <math.h>

// Problem dims
#define Bb   32
#define Tt   128
#define BT   4096      // B*T
#define DIN  32
#define H1   1024
#define Hh   2048
#define G3   6144      // 3*H
#define PEN  1024
#define Cc   64
#define Pp   4

// ---------------- scratch (static device globals; no allocation) -------------
__device__ float g_A1[BT * H1];       // after layer1
__device__ float g_A2[(size_t)BT * Hh];       // after layer2
__device__ float g_XP[(size_t)BT * G3];       // xp = A2 @ W_ih^T + b_ih
__device__ float g_H [(size_t)BT * Hh];       // GRU outputs per (b,t)
__device__ float g_S [BT * PEN];      // out_s
__device__ float g_HT[2][Hh * Bb];    // transposed h state [j][b], double buffered

// ---------------- init: zero h0 and output tail ------------------------------
__global__ void init_kernel(float* __restrict__ out, int out_size) {
    int i = blockIdx.x * blockDim.x + threadIdx.x;   // 65536 threads
    if (i < Hh * Bb) g_HT[0][i] = 0.0f;
    int tail = 28672 + i;
    if (tail < out_size) out[tail] = 0.0f;
}

// ---------------- SGEMM: C[M,N] = act(A[M,K] * W[N,K]^T + bias) --------------
// BM=BN=128, BK=16, 256 threads, 8x8 microtile. M,N % 128 == 0, K % 16 == 0.
template<bool RELU>
__global__ __launch_bounds__(256)
void sgemm_nt(const float* __restrict__ A, const float* __restrict__ W,
              const float* __restrict__ bias, float* __restrict__ Cd,
              int M, int N, int K) {
    __shared__ float As[16][128];
    __shared__ float Bs[16][128];
    const int tid = threadIdx.x;
    const int n0 = blockIdx.x * 128;
    const int m0 = blockIdx.y * 128;
    const int tx = tid & 15;         // n dir
    const int ty = tid >> 4;         // m dir

    float acc[8][8];
#pragma unroll
    for (int i = 0; i < 8; i++)
#pragma unroll
        for (int j = 0; j < 8; j++) acc[i][j] = 0.0f;

    for (int k0 = 0; k0 < K; k0 += 16) {
        // stage A and W tiles (k-major in smem)
#pragma unroll
        for (int i = 0; i < 2; i++) {
            int fi = tid * 2 + i;            // 0..511 float4s
            int m  = fi >> 2;
            int kq = (fi & 3) * 4;
            float4 va = *(const float4*)(A + (size_t)(m0 + m) * K + k0 + kq);
            As[kq + 0][m] = va.x; As[kq + 1][m] = va.y;
            As[kq + 2][m] = va.z; As[kq + 3][m] = va.w;
            float4 vb = *(const float4*)(W + (size_t)(n0 + m) * K + k0 + kq);
            Bs[kq + 0][m] = vb.x; Bs[kq + 1][m] = vb.y;
            Bs[kq + 2][m] = vb.z; Bs[kq + 3][m] = vb.w;
        }
        __syncthreads();

#pragma unroll
        for (int kk = 0; kk < 16; kk++) {
            float a[8], b[8];
            float4 a0 = *(const float4*)&As[kk][ty * 8];
            float4 a1 = *(const float4*)&As[kk][ty * 8 + 4];
            float4 b0 = *(const float4*)&Bs[kk][tx * 8];
            float4 b1 = *(const float4*)&Bs[kk][tx * 8 + 4];
            a[0]=a0.x; a[1]=a0.y; a[2]=a0.z; a[3]=a0.w;
            a[4]=a1.x; a[5]=a1.y; a[6]=a1.z; a[7]=a1.w;
            b[0]=b0.x; b[1]=b0.y; b[2]=b0.z; b[3]=b0.w;
            b[4]=b1.x; b[5]=b1.y; b[6]=b1.z; b[7]=b1.w;
#pragma unroll
            for (int i = 0; i < 8; i++)
#pragma unroll
                for (int j = 0; j < 8; j++)
                    acc[i][j] += a[i] * b[j];
        }
        __syncthreads();
    }

    // epilogue: bias + optional relu, float4 stores
#pragma unroll
    for (int i = 0; i < 8; i++) {
        size_t row = (size_t)(m0 + ty * 8 + i) * N + n0 + tx * 8;
#pragma unroll
        for (int j = 0; j < 8; j += 4) {
            float4 v;
            v.x = acc[i][j + 0] + bias[n0 + tx * 8 + j + 0];
            v.y = acc[i][j + 1] + bias[n0 + tx * 8 + j + 1];
            v.z = acc[i][j + 2] + bias[n0 + tx * 8 + j + 2];
            v.w = acc[i][j + 3] + bias[n0 + tx * 8 + j + 3];
            if (RELU) {
                v.x = fmaxf(v.x, 0.0f); v.y = fmaxf(v.y, 0.0f);
                v.z = fmaxf(v.z, 0.0f); v.w = fmaxf(v.w, 0.0f);
            }
            *(float4*)(Cd + row + j) = v;
        }
    }
}

// ---------------- GRU step (one launch per t) --------------------------------
// Block: 128 threads, handles j-tile of 16 (48 W rows) for all 32 batches.
// Thread layout for accumulation: bg = tid>>4 (8 groups of 4 batches),
//                                 g  = tid&15 (16 groups of 3 rows).
#define KC 64
__device__ __forceinline__ float sigmoidf_(float x) { return 1.0f / (1.0f + expf(-x)); }

__global__ __launch_bounds__(128)
void gru_step(const float* __restrict__ Whh, const float* __restrict__ bhh, int t) {
    const float* __restrict__ HTprev = g_HT[t & 1];
    float* __restrict__ HTnext = g_HT[(t & 1) ^ 1];

    __shared__ float ws[48][KC + 4];
    __shared__ float hs[32][KC + 4];
    __shared__ float hp[48][32];

    const int tid   = threadIdx.x;
    const int jbase = blockIdx.x * 16;
    const int bg    = tid >> 4;       // 0..7
    const int g     = tid & 15;       // 0..15
    const int r0    = g * 3;          // 3 rows per thread
    const int b0    = bg * 4;         // 4 batches per thread

    float acc[3][4];
#pragma unroll
    for (int e = 0; e < 3; e++)
#pragma unroll
        for (int bi = 0; bi < 4; bi++) acc[e][bi] = 0.0f;

    for (int k0 = 0; k0 < Hh; k0 += KC) {
        __syncthreads();
        // stage weights: 48 rows x KC, float4 loads (768 float4s / 128 threads = 6)
#pragma unroll
        for (int i = 0; i < 6; i++) {
            int fi = tid + i * 128;          // 0..767
            int rr = fi >> 4;                // /16
            int kq = (fi & 15) * 4;
            int grow = (rr >> 4) * Hh + jbase + (rr & 15);
            float4 v = *(const float4*)(Whh + (size_t)grow * Hh + k0 + kq);
            *(float4*)&ws[rr][kq] = v;
        }
        // stage h chunk transposed: hs[b][k] <- HTprev[(k0+k)*32 + b]
#pragma unroll
        for (int i = 0; i < 16; i++) {
            int idx = tid + i * 128;         // 0..2047
            int b = idx & 31;
            int k = idx >> 5;
            hs[b][k] = HTprev[(size_t)(k0 + k) * 32 + b];
        }
        __syncthreads();

#pragma unroll
        for (int kk = 0; kk < KC; kk += 4) {
            float4 w0 = *(const float4*)&ws[r0 + 0][kk];
            float4 w1 = *(const float4*)&ws[r0 + 1][kk];
            float4 w2 = *(const float4*)&ws[r0 + 2][kk];
#pragma unroll
            for (int bi = 0; bi < 4; bi++) {
                float4 h = *(const float4*)&hs[b0 + bi][kk];
                acc[0][bi] += w0.x*h.x + w0.y*h.y + w0.z*h.z + w0.w*h.w;
                acc[1][bi] += w1.x*h.x + w1.y*h.y + w1.z*h.z + w1.w*h.w;
                acc[2][bi] += w2.x*h.x + w2.y*h.y + w2.z*h.z + w2.w*h.w;
            }
        }
    }
    __syncthreads();
#pragma unroll
    for (int e = 0; e < 3; e++)
#pragma unroll
        for (int bi = 0; bi < 4; bi++)
            hp[r0 + e][b0 + bi] = acc[e][bi];
    __syncthreads();

    // gate phase: 16 j x 32 b = 512 outputs, 4 per thread
#pragma unroll
    for (int i = 0; i < 4; i++) {
        int oi = tid + i * 128;
        int b  = oi & 31;
        int jj = oi >> 5;                  // 0..15
        int j  = jbase + jj;
        size_t xoff = ((size_t)b * Tt + t) * G3 + j;
        float xr = g_XP[xoff];
        float xz = g_XP[xoff + Hh];
        float xn = g_XP[xoff + 2 * Hh];
        float hr = hp[jj][b]      + bhh[j];
        float hz = hp[16 + jj][b] + bhh[Hh + j];
        float hn = hp[32 + jj][b] + bhh[2 * Hh + j];
        float r = sigmoidf_(xr + hr);
        float z = sigmoidf_(xz + hz);
        float n = tanhf(xn + r * hn);
        float hprev = HTprev[(size_t)j * 32 + b];
        float hnew = (1.0f - z) * n + z * hprev;
        HTnext[(size_t)j * 32 + b] = hnew;
        g_H[((size_t)b * Tt + t) * Hh + j] = hnew;
    }
}

// ---------------- heads ------------------------------------------------------
__global__ __launch_bounds__(128)
void heads_kernel(const int* __restrict__ labels,
                  const float* __restrict__ W4, const float* __restrict__ b4,
                  const float* __restrict__ W5, const float* __restrict__ b5,
                  const float* __restrict__ W6, const float* __restrict__ b6,
                  const float* __restrict__ Wp, const float* __restrict__ bp,
                  float* __restrict__ out) {
    const int bt   = blockIdx.x;
    const int b    = bt >> 7;            // /128
    const int t    = bt & 127;
    const int lane = threadIdx.x & 31;
    const int w    = threadIdx.x >> 5;   // warp id 0..3
    const int lab  = labels[b];
    const float4* s4 = (const float4*)(g_S + (size_t)bt * PEN);

    for (int hh = w; hh < 7; hh += 4) {
        const float* Wrow;
        float bias;
        if (hh == 0)      { Wrow = W4 + (size_t)lab * PEN; bias = b4[lab]; }
        else if (hh == 1) { Wrow = W5 + (size_t)lab * PEN; bias = b5[lab]; }
        else if (hh == 2) { Wrow = W6 + (size_t)lab * PEN; bias = b6[lab]; }
        else {
            int p = hh - 3;
            Wrow = Wp + ((size_t)p * Cc + lab) * PEN;
            bias = bp[p * Cc + lab];
        }
        const float4* w4 = (const float4*)Wrow;
        float acc = 0.0f;
        for (int q = lane; q < PEN / 4; q += 32) {
            float4 sv = s4[q];
            float4 wv = w4[q];
            acc += sv.x * wv.x + sv.y * wv.y + sv.z * wv.z + sv.w * wv.w;
        }
#pragma unroll
        for (int off = 16; off > 0; off >>= 1)
            acc += __shfl_down_sync(0xffffffffu, acc, off);
        if (lane == 0) {
            float v = acc + bias;
            if (hh < 3) {
                out[hh * BT + bt] = v;
            } else {
                int p = hh - 3;
                out[3 * BT + ((size_t)p * Bb + b) * Tt + t] = 1.0f / (1.0f + expf(-v));
            }
        }
    }
}

// ---------------- launch -----------------------------------------------------
extern "C" void kernel_launch(void* const* d_in, const int* in_sizes, int n_in,
                              void* d_out, int out_size) {
    const float* x    = (const float*)d_in[0];
    const int*   lab  = (const int*)  d_in[1];
    const float* W1   = (const float*)d_in[2];
    const float* b1   = (const float*)d_in[3];
    const float* W2   = (const float*)d_in[4];
    const float* b2   = (const float*)d_in[5];
    const float* W_ih = (const float*)d_in[6];
    const float* b_ih = (const float*)d_in[7];
    const float* W_hh = (const float*)d_in[8];
    const float* b_hh = (const float*)d_in[9];
    const float* W3   = (const float*)d_in[10];
    const float* b3   = (const float*)d_in[11];
    const float* W4   = (const float*)d_in[12];
    const float* b4   = (const float*)d_in[13];
    const float* W5   = (const float*)d_in[14];
    const float* b5   = (const float*)d_in[15];
    const float* W6   = (const float*)d_in[16];
    const float* b6   = (const float*)d_in[17];
    const float* Wp   = (const float*)d_in[18];
    const float* bp   = (const float*)d_in[19];
    float* out = (float*)d_out;

    float *A1, *A2, *XP, *Hs, *S;
    cudaGetSymbolAddress((void**)&A1, g_A1);
    cudaGetSymbolAddress((void**)&A2, g_A2);
    cudaGetSymbolAddress((void**)&XP, g_XP);
    cudaGetSymbolAddress((void**)&Hs, g_H);
    cudaGetSymbolAddress((void**)&S,  g_S);

    init_kernel<<<256, 256>>>(out, out_size);

    // layer1: relu(x @ W1^T + b1)   M=4096 K=32 N=1024
    sgemm_nt<true><<<dim3(H1 / 128, BT / 128), 256>>>(x, W1, b1, A1, BT, H1, DIN);
    // layer2: relu(A1 @ W2^T + b2)  M=4096 K=1024 N=2048
    sgemm_nt<true><<<dim3(Hh / 128, BT / 128), 256>>>(A1, W2, b2, A2, BT, Hh, H1);
    // xp: A2 @ W_ih^T + b_ih        M=4096 K=2048 N=6144
    sgemm_nt<false><<<dim3(G3 / 128, BT / 128), 256>>>(A2, W_ih, b_ih, XP, BT, G3, Hh);
    // GRU recurrence
    for (int t = 0; t < Tt; t++)
        gru_step<<<Hh / 16, 128>>>(W_hh, b_hh, t);
    // layer3: relu(H @ W3^T + b3)   M=4096 K=2048 N=1024
    sgemm_nt<true><<<dim3(PEN / 128, BT / 128), 256>>>(Hs, W3, b3, S, BT, PEN, Hh);
    // heads
    heads_kernel<<<BT, 128>>>(lab, W4, b4, W5, b5, W6, b6, Wp, bp, out);
}

// round 2
// speedup vs baseline: 1.7281x; 1.7281x over previous
#include <cuda_runtime.h>
#include <cuda_bf16.h>
#include <math.h>
#include <stdint.h>

// Problem dims
#define Bb   32
#define Tt   128
#define BT   4096      // B*T
#define DIN  32
#define H1   1024
#define Hh   2048
#define G3   6144      // 3*H
#define PEN  1024
#define Cc   64
#define Pp   4

// ---------------- scratch (static device globals; no allocation) -------------
__device__ float g_A1[BT * H1];
__device__ float g_A2[(size_t)BT * Hh];
__device__ float g_XP[(size_t)BT * G3];
__device__ float g_H [(size_t)BT * Hh];
__device__ float g_S [BT * PEN];
__device__ float g_HT[2][Hh * Bb];            // fp32 h state [j][b], double buffered
__device__ uint16_t g_Whh_hi[(size_t)G3 * Hh];  // bf16 splits of W_hh
__device__ uint16_t g_Whh_lo[(size_t)G3 * Hh];
__device__ uint16_t g_hbf[2][2][Bb * Hh];     // [buf][hi/lo][b][k] bf16 h state

// ---------------- helpers ----------------------------------------------------
__device__ __forceinline__ void split_bf16(float a, uint16_t& h, uint16_t& l) {
    __nv_bfloat16 bh = __float2bfloat16_rn(a);
    float r = a - __bfloat162float(bh);
    __nv_bfloat16 bl = __float2bfloat16_rn(r);
    h = __bfloat16_as_ushort(bh);
    l = __bfloat16_as_ushort(bl);
}
__device__ __forceinline__ uint32_t pack16(uint16_t lo, uint16_t hi) {
    return (uint32_t)lo | ((uint32_t)hi << 16);
}
__device__ __forceinline__ uint32_t lds_u32(const uint16_t* base, int idx) {
    return *(const uint32_t*)(base + idx);
}
#define MMA_BF16(c0,c1,c2,c3,a0,a1,a2,a3,b0,b1) \
    asm volatile("mma.sync.aligned.m16n8k16.row.col.f32.bf16.bf16.f32 " \
        "{%0,%1,%2,%3},{%4,%5,%6,%7},{%8,%9},{%0,%1,%2,%3};" \
        : "+f"(c0),"+f"(c1),"+f"(c2),"+f"(c3) \
        : "r"(a0),"r"(a1),"r"(a2),"r"(a3),"r"(b0),"r"(b1))

__device__ __forceinline__ float sigmoidf_(float x) { return 1.0f / (1.0f + expf(-x)); }

// ---------------- init: zero h0 (fp32 + bf16) and output tail ----------------
__global__ void init_kernel(float* __restrict__ out, int out_size) {
    int i = blockIdx.x * blockDim.x + threadIdx.x;   // 65536 threads
    if (i < Hh * Bb) {
        g_HT[0][i] = 0.0f;
        g_hbf[0][0][i] = 0;
        g_hbf[0][1][i] = 0;
    }
    int tail = 28672 + i;
    if (tail < out_size) out[tail] = 0.0f;
}

// ---------------- W_hh split-bf16 conversion ---------------------------------
__global__ __launch_bounds__(256)
void convert_whh(const float* __restrict__ W) {
    size_t base = ((size_t)blockIdx.x * 256 + threadIdx.x) * 8;
    float4 v0 = *(const float4*)(W + base);
    float4 v1 = *(const float4*)(W + base + 4);
    uint16_t h[8], l[8];
    split_bf16(v0.x, h[0], l[0]); split_bf16(v0.y, h[1], l[1]);
    split_bf16(v0.z, h[2], l[2]); split_bf16(v0.w, h[3], l[3]);
    split_bf16(v1.x, h[4], l[4]); split_bf16(v1.y, h[5], l[5]);
    split_bf16(v1.z, h[6], l[6]); split_bf16(v1.w, h[7], l[7]);
    uint4 ph, pl;
    ph.x = pack16(h[0], h[1]); ph.y = pack16(h[2], h[3]);
    ph.z = pack16(h[4], h[5]); ph.w = pack16(h[6], h[7]);
    pl.x = pack16(l[0], l[1]); pl.y = pack16(l[2], l[3]);
    pl.z = pack16(l[4], l[5]); pl.w = pack16(l[6], l[7]);
    *(uint4*)(g_Whh_hi + base) = ph;
    *(uint4*)(g_Whh_lo + base) = pl;
}

// ---------------- tensor-core split-bf16 GEMM --------------------------------
// C[M,N] = act(A[M,K] @ W[N,K]^T + bias). BM=BN=128, BK=32, 256 threads (8 warps).
// Warp grid 4(m) x 2(n); warp tile 32x64; mma m16n8k16.
#define SGA_LD 40   // smem row stride in bf16 elems (pad 8)
template<bool RELU>
__global__ __launch_bounds__(256)
void sgemm_tc(const float* __restrict__ A, const float* __restrict__ W,
              const float* __restrict__ bias, float* __restrict__ Cd,
              int M, int N, int K) {
    __shared__ uint16_t Ahi[128 * SGA_LD], Alo[128 * SGA_LD];
    __shared__ uint16_t Bhi[128 * SGA_LD], Blo[128 * SGA_LD];

    const int tid  = threadIdx.x;
    const int lane = tid & 31;
    const int wid  = tid >> 5;
    const int wm   = (wid & 3) * 32;     // warp m offset
    const int wn   = (wid >> 2) * 64;    // warp n offset
    const int n0 = blockIdx.x * 128;
    const int m0 = blockIdx.y * 128;
    const int gr = lane >> 2;            // fragment row
    const int c2 = (lane & 3) * 2;       // fragment k-pair col

    float acc[2][8][4];
#pragma unroll
    for (int i = 0; i < 2; i++)
#pragma unroll
        for (int j = 0; j < 8; j++)
#pragma unroll
            for (int e = 0; e < 4; e++) acc[i][j][e] = 0.0f;

    for (int k0 = 0; k0 < K; k0 += 32) {
        __syncthreads();
        // stage + split-convert: 128x32 fp32 -> bf16 hi/lo, both A and W tiles
#pragma unroll
        for (int i = 0; i < 4; i++) {
            int f   = tid + i * 256;         // 0..1023 float4s
            int row = f >> 3;
            int kq  = (f & 7) * 4;
            float4 va = *(const float4*)(A + (size_t)(m0 + row) * K + k0 + kq);
            uint16_t h0,h1,h2,h3,l0,l1,l2,l3;
            split_bf16(va.x,h0,l0); split_bf16(va.y,h1,l1);
            split_bf16(va.z,h2,l2); split_bf16(va.w,h3,l3);
            int so = row * SGA_LD + kq;
            *(uint32_t*)(Ahi + so)     = pack16(h0,h1);
            *(uint32_t*)(Ahi + so + 2) = pack16(h2,h3);
            *(uint32_t*)(Alo + so)     = pack16(l0,l1);
            *(uint32_t*)(Alo + so + 2) = pack16(l2,l3);
            float4 vb = *(const float4*)(W + (size_t)(n0 + row) * K + k0 + kq);
            split_bf16(vb.x,h0,l0); split_bf16(vb.y,h1,l1);
            split_bf16(vb.z,h2,l2); split_bf16(vb.w,h3,l3);
            *(uint32_t*)(Bhi + so)     = pack16(h0,h1);
            *(uint32_t*)(Bhi + so + 2) = pack16(h2,h3);
            *(uint32_t*)(Blo + so)     = pack16(l0,l1);
            *(uint32_t*)(Blo + so + 2) = pack16(l2,l3);
        }
        __syncthreads();

#pragma unroll
        for (int ks = 0; ks < 2; ks++) {
            const int kb = ks * 16;
            // A fragments: 2 m-tiles, hi and lo
            uint32_t ah[2][4], al[2][4];
#pragma unroll
            for (int mt = 0; mt < 2; mt++) {
                int r = wm + mt * 16 + gr;
                ah[mt][0] = lds_u32(Ahi, r * SGA_LD + kb + c2);
                ah[mt][1] = lds_u32(Ahi, (r + 8) * SGA_LD + kb + c2);
                ah[mt][2] = lds_u32(Ahi, r * SGA_LD + kb + c2 + 8);
                ah[mt][3] = lds_u32(Ahi, (r + 8) * SGA_LD + kb + c2 + 8);
                al[mt][0] = lds_u32(Alo, r * SGA_LD + kb + c2);
                al[mt][1] = lds_u32(Alo, (r + 8) * SGA_LD + kb + c2);
                al[mt][2] = lds_u32(Alo, r * SGA_LD + kb + c2 + 8);
                al[mt][3] = lds_u32(Alo, (r + 8) * SGA_LD + kb + c2 + 8);
            }
#pragma unroll
            for (int nt = 0; nt < 8; nt++) {
                int n = wn + nt * 8 + gr;
                uint32_t bh0 = lds_u32(Bhi, n * SGA_LD + kb + c2);
                uint32_t bh1 = lds_u32(Bhi, n * SGA_LD + kb + c2 + 8);
                uint32_t bl0 = lds_u32(Blo, n * SGA_LD + kb + c2);
                uint32_t bl1 = lds_u32(Blo, n * SGA_LD + kb + c2 + 8);
#pragma unroll
                for (int mt = 0; mt < 2; mt++) {
                    MMA_BF16(acc[mt][nt][0], acc[mt][nt][1], acc[mt][nt][2], acc[mt][nt][3],
                             ah[mt][0], ah[mt][1], ah[mt][2], ah[mt][3], bh0, bh1);
                    MMA_BF16(acc[mt][nt][0], acc[mt][nt][1], acc[mt][nt][2], acc[mt][nt][3],
                             ah[mt][0], ah[mt][1], ah[mt][2], ah[mt][3], bl0, bl1);
                    MMA_BF16(acc[mt][nt][0], acc[mt][nt][1], acc[mt][nt][2], acc[mt][nt][3],
                             al[mt][0], al[mt][1], al[mt][2], al[mt][3], bh0, bh1);
                }
            }
        }
    }

    // epilogue: bias + optional relu
#pragma unroll
    for (int mt = 0; mt < 2; mt++) {
        int r  = m0 + wm + mt * 16 + gr;
#pragma unroll
        for (int nt = 0; nt < 8; nt++) {
            int cb = n0 + wn + nt * 8 + c2;
            float bx = bias[cb], by = bias[cb + 1];
            float v0 = acc[mt][nt][0] + bx;
            float v1 = acc[mt][nt][1] + by;
            float v2 = acc[mt][nt][2] + bx;
            float v3 = acc[mt][nt][3] + by;
            if (RELU) {
                v0 = fmaxf(v0, 0.0f); v1 = fmaxf(v1, 0.0f);
                v2 = fmaxf(v2, 0.0f); v3 = fmaxf(v3, 0.0f);
            }
            *(float2*)(Cd + (size_t)r * N + cb)       = make_float2(v0, v1);
            *(float2*)(Cd + (size_t)(r + 8) * N + cb) = make_float2(v2, v3);
        }
    }
}

// ---------------- GRU step (tensor core) -------------------------------------
// 128 blocks; block owns j-tile of 16 (48 W_hh rows: r/z/n gates), all 32 batches.
// 384 threads = 12 warps: mt = wid&1 (batch half), nt = wid>>1 (n-tile of 8 rows).
#define GRU_LD 72   // smem row stride (64 + 8 pad)
__global__ __launch_bounds__(384)
void gru_step_tc(const float* __restrict__ bhh, int t) {
    __shared__ uint16_t Whi_s[48 * GRU_LD], Wlo_s[48 * GRU_LD];
    __shared__ uint16_t Hhi_s[32 * GRU_LD], Hlo_s[32 * GRU_LD];
    __shared__ float hp_s[48][33];

    const int tid  = threadIdx.x;
    const int lane = tid & 31;
    const int wid  = tid >> 5;
    const int mt   = wid & 1;
    const int nt   = wid >> 1;          // 0..5
    const int gr   = lane >> 2;
    const int c2   = (lane & 3) * 2;
    const int jbase = blockIdx.x * 16;

    const uint16_t* __restrict__ hH = g_hbf[t & 1][0];
    const uint16_t* __restrict__ hL = g_hbf[t & 1][1];

    float c0 = 0.f, c1 = 0.f, c2a = 0.f, c3 = 0.f;

    for (int k0 = 0; k0 < Hh; k0 += 64) {
        __syncthreads();
        {   // stage W: 48 rows x 64 bf16 (hi+lo); 384 uint4 per array, 1/thread
            int r  = tid >> 3;
            int kq = (tid & 7) * 8;
            int g  = r >> 4, jj = r & 15;
            size_t grow = (size_t)(g * Hh + jbase + jj) * Hh + k0 + kq;
            *(uint4*)(Whi_s + r * GRU_LD + kq) = *(const uint4*)(g_Whh_hi + grow);
            *(uint4*)(Wlo_s + r * GRU_LD + kq) = *(const uint4*)(g_Whh_lo + grow);
        }
        if (tid < 256) {   // stage h: 32 x 64 bf16 (hi+lo)
            int b  = tid >> 3;
            int kq = (tid & 7) * 8;
            *(uint4*)(Hhi_s + b * GRU_LD + kq) = *(const uint4*)(hH + b * Hh + k0 + kq);
            *(uint4*)(Hlo_s + b * GRU_LD + kq) = *(const uint4*)(hL + b * Hh + k0 + kq);
        }
        __syncthreads();

#pragma unroll
        for (int ks = 0; ks < 4; ks++) {
            const int kb = ks * 16;
            int rA = mt * 16 + gr;
            uint32_t ah0 = lds_u32(Hhi_s, rA * GRU_LD + kb + c2);
            uint32_t ah1 = lds_u32(Hhi_s, (rA + 8) * GRU_LD + kb + c2);
            uint32_t ah2 = lds_u32(Hhi_s, rA * GRU_LD + kb + c2 + 8);
            uint32_t ah3 = lds_u32(Hhi_s, (rA + 8) * GRU_LD + kb + c2 + 8);
            uint32_t al0 = lds_u32(Hlo_s, rA * GRU_LD + kb + c2);
            uint32_t al1 = lds_u32(Hlo_s, (rA + 8) * GRU_LD + kb + c2);
            uint32_t al2 = lds_u32(Hlo_s, rA * GRU_LD + kb + c2 + 8);
            uint32_t al3 = lds_u32(Hlo_s, (rA + 8) * GRU_LD + kb + c2 + 8);
            int rB = nt * 8 + gr;
            uint32_t bh0 = lds_u32(Whi_s, rB * GRU_LD + kb + c2);
            uint32_t bh1 = lds_u32(Whi_s, rB * GRU_LD + kb + c2 + 8);
            uint32_t bl0 = lds_u32(Wlo_s, rB * GRU_LD + kb + c2);
            uint32_t bl1 = lds_u32(Wlo_s, rB * GRU_LD + kb + c2 + 8);
            MMA_BF16(c0, c1, c2a, c3, ah0, ah1, ah2, ah3, bh0, bh1);
            MMA_BF16(c0, c1, c2a, c3, ah0, ah1, ah2, ah3, bl0, bl1);
            MMA_BF16(c0, c1, c2a, c3, al0, al1, al2, al3, bh0, bh1);
        }
    }
    __syncthreads();
    {   // scatter accum into hp_s[gate_row][batch]
        int col = nt * 8 + c2;
        int row = mt * 16 + gr;
        hp_s[col][row]         = c0;
        hp_s[col + 1][row]     = c1;
        hp_s[col][row + 8]     = c2a;
        hp_s[col + 1][row + 8] = c3;
    }
    __syncthreads();

    const float* __restrict__ HTprev = g_HT[t & 1];
    float* __restrict__ HTnext = g_HT[(t & 1) ^ 1];
    uint16_t* __restrict__ hHn = g_hbf[(t & 1) ^ 1][0];
    uint16_t* __restrict__ hLn = g_hbf[(t & 1) ^ 1][1];

#pragma unroll
    for (int i = 0; i < 2; i++) {
        int oi = tid + i * 384;
        if (oi < 512) {
            int b  = oi & 31;
            int jj = oi >> 5;
            int j  = jbase + jj;
            size_t xoff = ((size_t)b * Tt + t) * G3 + j;
            float xr = g_XP[xoff];
            float xz = g_XP[xoff + Hh];
            float xn = g_XP[xoff + 2 * Hh];
            float hr = hp_s[jj][b]      + bhh[j];
            float hz = hp_s[16 + jj][b] + bhh[Hh + j];
            float hn = hp_s[32 + jj][b] + bhh[2 * Hh + j];
            float r = sigmoidf_(xr + hr);
            float z = sigmoidf_(xz + hz);
            float n = tanhf(xn + r * hn);
            float hprev = HTprev[(size_t)j * 32 + b];
            float hnew = (1.0f - z) * n + z * hprev;
            HTnext[(size_t)j * 32 + b] = hnew;
            g_H[((size_t)b * Tt + t) * Hh + j] = hnew;
            uint16_t hh, hl;
            split_bf16(hnew, hh, hl);
            hHn[(size_t)b * Hh + j] = hh;
            hLn[(size_t)b * Hh + j] = hl;
        }
    }
}

// ---------------- heads ------------------------------------------------------
__global__ __launch_bounds__(128)
void heads_kernel(const int* __restrict__ labels,
                  const float* __restrict__ W4, const float* __restrict__ b4,
                  const float* __restrict__ W5, const float* __restrict__ b5,
                  const float* __restrict__ W6, const float* __restrict__ b6,
                  const float* __restrict__ Wp, const float* __restrict__ bp,
                  float* __restrict__ out) {
    const int bt   = blockIdx.x;
    const int b    = bt >> 7;
    const int t    = bt & 127;
    const int lane = threadIdx.x & 31;
    const int w    = threadIdx.x >> 5;
    const int lab  = labels[b];
    const float4* s4 = (const float4*)(g_S + (size_t)bt * PEN);

    for (int hh = w; hh < 7; hh += 4) {
        const float* Wrow;
        float bias;
        if (hh == 0)      { Wrow = W4 + (size_t)lab * PEN; bias = b4[lab]; }
        else if (hh == 1) { Wrow = W5 + (size_t)lab * PEN; bias = b5[lab]; }
        else if (hh == 2) { Wrow = W6 + (size_t)lab * PEN; bias = b6[lab]; }
        else {
            int p = hh - 3;
            Wrow = Wp + ((size_t)p * Cc + lab) * PEN;
            bias = bp[p * Cc + lab];
        }
        const float4* w4 = (const float4*)Wrow;
        float acc = 0.0f;
        for (int q = lane; q < PEN / 4; q += 32) {
            float4 sv = s4[q];
            float4 wv = w4[q];
            acc += sv.x * wv.x + sv.y * wv.y + sv.z * wv.z + sv.w * wv.w;
        }
#pragma unroll
        for (int off = 16; off > 0; off >>= 1)
            acc += __shfl_down_sync(0xffffffffu, acc, off);
        if (lane == 0) {
            float v = acc + bias;
            if (hh < 3) {
                out[hh * BT + bt] = v;
            } else {
                int p = hh - 3;
                out[3 * BT + ((size_t)p * Bb + b) * Tt + t] = 1.0f / (1.0f + expf(-v));
            }
        }
    }
}

// ---------------- launch -----------------------------------------------------
extern "C" void kernel_launch(void* const* d_in, const int* in_sizes, int n_in,
                              void* d_out, int out_size) {
    const float* x    = (const float*)d_in[0];
    const int*   lab  = (const int*)  d_in[1];
    const float* W1   = (const float*)d_in[2];
    const float* b1   = (const float*)d_in[3];
    const float* W2   = (const float*)d_in[4];
    const float* b2   = (const float*)d_in[5];
    const float* W_ih = (const float*)d_in[6];
    const float* b_ih = (const float*)d_in[7];
    const float* W_hh = (const float*)d_in[8];
    const float* b_hh = (const float*)d_in[9];
    const float* W3   = (const float*)d_in[10];
    const float* b3   = (const float*)d_in[11];
    const float* W4   = (const float*)d_in[12];
    const float* b4   = (const float*)d_in[13];
    const float* W5   = (const float*)d_in[14];
    const float* b5   = (const float*)d_in[15];
    const float* W6   = (const float*)d_in[16];
    const float* b6   = (const float*)d_in[17];
    const float* Wp   = (const float*)d_in[18];
    const float* bp   = (const float*)d_in[19];
    float* out = (float*)d_out;

    float *A1, *A2, *XP, *Hs, *S;
    cudaGetSymbolAddress((void**)&A1, g_A1);
    cudaGetSymbolAddress((void**)&A2, g_A2);
    cudaGetSymbolAddress((void**)&XP, g_XP);
    cudaGetSymbolAddress((void**)&Hs, g_H);
    cudaGetSymbolAddress((void**)&S,  g_S);

    init_kernel<<<256, 256>>>(out, out_size);
    convert_whh<<<(G3 * Hh) / (256 * 8), 256>>>(W_hh);

    // layer1: relu(x @ W1^T + b1)   M=4096 K=32 N=1024
    sgemm_tc<true><<<dim3(H1 / 128, BT / 128), 256>>>(x, W1, b1, A1, BT, H1, DIN);
    // layer2: relu(A1 @ W2^T + b2)  M=4096 K=1024 N=2048
    sgemm_tc<true><<<dim3(Hh / 128, BT / 128), 256>>>(A1, W2, b2, A2, BT, Hh, H1);
    // xp: A2 @ W_ih^T + b_ih        M=4096 K=2048 N=6144
    sgemm_tc<false><<<dim3(G3 / 128, BT / 128), 256>>>(A2, W_ih, b_ih, XP, BT, G3, Hh);
    // GRU recurrence (tensor-core steps)
    for (int t = 0; t < Tt; t++)
        gru_step_tc<<<Hh / 16, 384>>>(b_hh, t);
    // layer3: relu(H @ W3^T + b3)   M=4096 K=2048 N=1024
    sgemm_tc<true><<<dim3(PEN / 128, BT / 128), 256>>>(Hs, W3, b3, S, BT, PEN, Hh);
    // heads
    heads_kernel<<<BT, 128>>>(lab, W4, b4, W5, b5, W6, b6, Wp, bp, out);
}

// round 4
// speedup vs baseline: 2.2518x; 1.3031x over previous
#include <cuda_runtime.h>
#include <cuda_bf16.h>
#include <math.h>
#include <stdint.h>

#define Bb   32
#define Tt   128
#define BT   4096
#define DIN  32
#define H1   1024
#define Hh   2048
#define G3   6144
#define PEN  1024
#define Cc   64
#define Pp   4

typedef __nv_bfloat16 bf16;

// ---------------- device globals (no allocation) -----------------------------
__device__ __align__(16) float g_XP[(size_t)BT * G3];
__device__ __align__(16) float g_S [BT * PEN];
__device__ __align__(16) float g_HT[2][Hh * Bb];
__device__ __align__(16) bf16  g_xb  [2][BT * DIN];
__device__ __align__(16) bf16  g_W1b [2][H1 * DIN];
__device__ __align__(16) bf16  g_W2b [2][(size_t)Hh * H1];
__device__ __align__(16) bf16  g_Wihb[2][(size_t)G3 * Hh];
__device__ __align__(16) bf16  g_Whhb[2][(size_t)G3 * Hh];
__device__ __align__(16) bf16  g_W3b [2][(size_t)PEN * Hh];
__device__ __align__(16) bf16  g_A1b [2][(size_t)BT * H1];
__device__ __align__(16) bf16  g_A2b [2][(size_t)BT * Hh];
__device__ __align__(16) bf16  g_Hb  [2][(size_t)BT * Hh];
__device__ __align__(16) bf16  g_hstate[2][2][Bb * Hh];   // [buf][hi/lo][b*Hh+k]
__device__ unsigned g_gen;
__device__ unsigned g_count;

// ---------------- helpers ----------------------------------------------------
__device__ __forceinline__ void split_bf16(float a, uint16_t& h, uint16_t& l) {
    __nv_bfloat16 bh = __float2bfloat16_rn(a);
    float r = a - __bfloat162float(bh);
    __nv_bfloat16 bl = __float2bfloat16_rn(r);
    h = __bfloat16_as_ushort(bh);
    l = __bfloat16_as_ushort(bl);
}
__device__ __forceinline__ uint32_t pack16(uint16_t a, uint16_t b) {
    return (uint32_t)a | ((uint32_t)b << 16);
}
__device__ __forceinline__ void cp16(uint32_t sa, const void* g) {
    asm volatile("cp.async.cg.shared.global [%0], [%1], 16;" :: "r"(sa), "l"(g));
}
#define CP_COMMIT asm volatile("cp.async.commit_group;")
#define CP_WAIT1  asm volatile("cp.async.wait_group 1;")
#define CP_WAIT0  asm volatile("cp.async.wait_group 0;")

__device__ __forceinline__ void ldsm4f(uint32_t* r, const uint16_t* arr, int LD,
                                       int rowBase, int col, int lane) {
    int q = lane >> 3, rr = lane & 7;
    const uint16_t* p = arr + (rowBase + rr + ((q & 1) << 3)) * LD + col + ((q >> 1) << 3);
    uint32_t a = (uint32_t)__cvta_generic_to_shared(p);
    asm volatile("ldmatrix.sync.aligned.m8n8.x4.shared.b16 {%0,%1,%2,%3}, [%4];"
        : "=r"(r[0]), "=r"(r[1]), "=r"(r[2]), "=r"(r[3]) : "r"(a));
}
__device__ __forceinline__ void ldsm2f(uint32_t* r, const uint16_t* arr, int LD,
                                       int rowBase, int col, int lane) {
    int l = lane & 15; int q = l >> 3, rr = l & 7;
    const uint16_t* p = arr + (rowBase + rr) * LD + col + (q << 3);
    uint32_t a = (uint32_t)__cvta_generic_to_shared(p);
    asm volatile("ldmatrix.sync.aligned.m8n8.x2.shared.b16 {%0,%1}, [%2];"
        : "=r"(r[0]), "=r"(r[1]) : "r"(a));
}
#define MMA4(c, af, b0, b1) \
    asm volatile("mma.sync.aligned.m16n8k16.row.col.f32.bf16.bf16.f32 " \
        "{%0,%1,%2,%3},{%4,%5,%6,%7},{%8,%9},{%0,%1,%2,%3};" \
        : "+f"((c)[0]),"+f"((c)[1]),"+f"((c)[2]),"+f"((c)[3]) \
        : "r"((af)[0]),"r"((af)[1]),"r"((af)[2]),"r"((af)[3]),"r"(b0),"r"(b1))

__device__ __forceinline__ float sigmoidf_(float x) { return 1.0f / (1.0f + expf(-x)); }

// ---------------- init: zero h state, barrier, AND output tail ---------------
__global__ void init_kernel(float* __restrict__ out, int out_size) {
    int i = blockIdx.x * blockDim.x + threadIdx.x;   // 65536 threads
    if (i < Hh * Bb) {
        g_HT[0][i] = 0.0f;
        g_hstate[0][0][i] = __ushort_as_bfloat16((uint16_t)0);
        g_hstate[0][1][i] = __ushort_as_bfloat16((uint16_t)0);
    }
    int tail = 28672 + i;          // heads write [0, 28672); zero the rest
    if (tail < out_size) out[tail] = 0.0f;
    if (i == 0) { g_gen = 0u; g_count = 0u; }
}

// ---------------- fp32 -> split bf16 hi/lo -----------------------------------
__global__ __launch_bounds__(256)
void convert_split_k(const float* __restrict__ src, bf16* __restrict__ hi,
                     bf16* __restrict__ lo) {
    size_t base = ((size_t)blockIdx.x * 256 + threadIdx.x) * 8;
    float4 v0 = *(const float4*)(src + base);
    float4 v1 = *(const float4*)(src + base + 4);
    uint16_t h[8], l[8];
    split_bf16(v0.x,h[0],l[0]); split_bf16(v0.y,h[1],l[1]);
    split_bf16(v0.z,h[2],l[2]); split_bf16(v0.w,h[3],l[3]);
    split_bf16(v1.x,h[4],l[4]); split_bf16(v1.y,h[5],l[5]);
    split_bf16(v1.z,h[6],l[6]); split_bf16(v1.w,h[7],l[7]);
    uint4 ph, pl;
    ph.x = pack16(h[0],h[1]); ph.y = pack16(h[2],h[3]);
    ph.z = pack16(h[4],h[5]); ph.w = pack16(h[6],h[7]);
    pl.x = pack16(l[0],l[1]); pl.y = pack16(l[2],l[3]);
    pl.z = pack16(l[4],l[5]); pl.w = pack16(l[6],l[7]);
    *(uint4*)(hi + base) = ph;
    *(uint4*)(lo + base) = pl;
}

// ---------------- 3-pass split-bf16 tensor-core GEMM -------------------------
// C[M,N] = act(A[M,K] @ W[N,K]^T + bias). BM=BN=128, BK=32, 256 thr, cp.async x2.
#define SLD 40
#define GEMM_SMEM (2 * 4 * 128 * SLD * 2)   // 81920 B

template<bool RELU, bool BF16OUT>
__global__ __launch_bounds__(256)
void gemm3p(const bf16* __restrict__ Ah, const bf16* __restrict__ Al,
            const bf16* __restrict__ Wh, const bf16* __restrict__ Wl,
            const float* __restrict__ bias,
            float* __restrict__ outF, bf16* __restrict__ outH, bf16* __restrict__ outL,
            int M, int N, int K) {
    extern __shared__ char raw[];
    uint16_t* sm = (uint16_t*)raw;
    const int tid = threadIdx.x, lane = tid & 31, wid = tid >> 5;
    const int wm = (wid & 3) * 32, wn = (wid >> 2) * 64;
    const int n0 = blockIdx.x * 128, m0 = blockIdx.y * 128;
    const int gr = lane >> 2, c2 = (lane & 3) * 2;
    const int row0 = tid >> 2, seg = (tid & 3) << 3;
    const uint32_t smBase = (uint32_t)__cvta_generic_to_shared(sm);

    const bf16* gAh = Ah + (size_t)m0 * K;
    const bf16* gAl = Al + (size_t)m0 * K;
    const bf16* gWh = Wh + (size_t)n0 * K;
    const bf16* gWl = Wl + (size_t)n0 * K;

    float acc[2][8][4];
#pragma unroll
    for (int i = 0; i < 2; i++)
#pragma unroll
        for (int j = 0; j < 8; j++)
#pragma unroll
            for (int e = 0; e < 4; e++) acc[i][j][e] = 0.0f;

#define GISS(ptr, aidx, rep, s, k0) \
    cp16(smBase + (uint32_t)((((s)*4+(aidx))*(128*SLD)) + (row0 + (rep)*64)*SLD + seg)*2, \
         (ptr) + (size_t)(row0 + (rep)*64) * K + (k0) + seg)
#define GEMM_ISSUE(s, k0) do { \
    GISS(gAh, 0, 0, s, k0); GISS(gAh, 0, 1, s, k0); \
    GISS(gAl, 1, 0, s, k0); GISS(gAl, 1, 1, s, k0); \
    GISS(gWh, 2, 0, s, k0); GISS(gWh, 2, 1, s, k0); \
    GISS(gWl, 3, 0, s, k0); GISS(gWl, 3, 1, s, k0); } while (0)

    const int nch = K >> 5;
    GEMM_ISSUE(0, 0);
    CP_COMMIT;
#pragma unroll 1
    for (int c = 0; c < nch; c++) {
        if (c + 1 < nch) { GEMM_ISSUE((c + 1) & 1, (c + 1) << 5); CP_COMMIT; CP_WAIT1; }
        else { CP_WAIT0; }
        __syncthreads();
        const int st = c & 1;
        const uint16_t* Ah_s = sm + (st * 4 + 0) * (128 * SLD);
        const uint16_t* Al_s = sm + (st * 4 + 1) * (128 * SLD);
        const uint16_t* Wh_s = sm + (st * 4 + 2) * (128 * SLD);
        const uint16_t* Wl_s = sm + (st * 4 + 3) * (128 * SLD);
#pragma unroll
        for (int ks = 0; ks < 2; ks++) {
            const int kb = ks * 16;
            uint32_t ahf[2][4], alf[2][4];
#pragma unroll
            for (int mt = 0; mt < 2; mt++) {
                ldsm4f(ahf[mt], Ah_s, SLD, wm + mt * 16, kb, lane);
                ldsm4f(alf[mt], Al_s, SLD, wm + mt * 16, kb, lane);
            }
#pragma unroll
            for (int p = 0; p < 4; p++) {
                uint32_t bh[4], bl[4];
                ldsm4f(bh, Wh_s, SLD, wn + p * 16, kb, lane);
                ldsm4f(bl, Wl_s, SLD, wn + p * 16, kb, lane);
#pragma unroll
                for (int e = 0; e < 2; e++) {
                    const int nt = p * 2 + e;
#pragma unroll
                    for (int mt = 0; mt < 2; mt++) {
                        MMA4(acc[mt][nt], ahf[mt], bh[e], bh[2 + e]);
                        MMA4(acc[mt][nt], ahf[mt], bl[e], bl[2 + e]);
                        MMA4(acc[mt][nt], alf[mt], bh[e], bh[2 + e]);
                    }
                }
            }
        }
        __syncthreads();
    }

    // epilogue
#pragma unroll
    for (int mt = 0; mt < 2; mt++) {
        const int r = m0 + wm + mt * 16 + gr;
#pragma unroll
        for (int nt = 0; nt < 8; nt++) {
            const int cb = n0 + wn + nt * 8 + c2;
            float bx = bias[cb], by = bias[cb + 1];
            float v0 = acc[mt][nt][0] + bx;
            float v1 = acc[mt][nt][1] + by;
            float v2 = acc[mt][nt][2] + bx;
            float v3 = acc[mt][nt][3] + by;
            if (RELU) {
                v0 = fmaxf(v0, 0.0f); v1 = fmaxf(v1, 0.0f);
                v2 = fmaxf(v2, 0.0f); v3 = fmaxf(v3, 0.0f);
            }
            if (BF16OUT) {
                uint16_t h0,l0,h1,l1;
                split_bf16(v0,h0,l0); split_bf16(v1,h1,l1);
                *(uint32_t*)(outH + (size_t)r * N + cb) = pack16(h0,h1);
                *(uint32_t*)(outL + (size_t)r * N + cb) = pack16(l0,l1);
                split_bf16(v2,h0,l0); split_bf16(v3,h1,l1);
                *(uint32_t*)(outH + (size_t)(r + 8) * N + cb) = pack16(h0,h1);
                *(uint32_t*)(outL + (size_t)(r + 8) * N + cb) = pack16(l0,l1);
            } else {
                *(float2*)(outF + (size_t)r * N + cb)       = make_float2(v0, v1);
                *(float2*)(outF + (size_t)(r + 8) * N + cb) = make_float2(v2, v3);
            }
        }
    }
}

// ---------------- persistent GRU ---------------------------------------------
// 128 blocks x 384 threads. Block owns 16 j's (48 gate rows). W_hh hi slice
// resident in smem for all 128 steps; W_lo + h hi/lo streamed via cp.async.
#define WLD 2056
#define GLD 72
#define GRU_W_ELEMS (48 * WLD)            // 98688
#define GRU_STG_ELEMS 8064                // per stage: 48*72 + 2*32*72
#define GRU_SMEM ((GRU_W_ELEMS + 2 * GRU_STG_ELEMS) * 2)   // 229,632 B

__global__ __launch_bounds__(384)
void gru_persist(const float* __restrict__ bhh) {
    extern __shared__ char raw[];
    uint16_t* sm = (uint16_t*)raw;
    const int tid = threadIdx.x, lane = tid & 31, wid = tid >> 5;
    const int nt = wid % 6, mt = wid / 6;
    const int jbase = blockIdx.x * 16;
    const int gr = lane >> 2, cc2 = (lane & 3) * 2;
    const uint32_t smBase = (uint32_t)__cvta_generic_to_shared(sm);

    // prologue: W_hh hi slice into smem (48 rows x 2048)
    for (int i = tid; i < 48 * 256; i += 384) {
        int row = i >> 8;
        int s8  = (i & 255) << 3;
        int g = row >> 4, jj = row & 15;
        const uint4* gp = (const uint4*)(g_Whhb[0] + (size_t)(g * Hh + jbase + jj) * Hh + s8);
        *(uint4*)(sm + row * WLD + s8) = *gp;
    }
    __syncthreads();

    // staging descriptors (constant across steps)
    const int wrow = tid >> 3, wseg = (tid & 7) << 3;
    const bf16* wlo_rp = g_Whhb[1] +
        (size_t)((wrow >> 4) * Hh + jbase + (wrow & 15)) * Hh + wseg;
    const uint32_t wlo_so = (uint32_t)(wrow * GLD + wseg);
    const size_t h_go = (size_t)wrow * Hh + wseg;   // wrow<32 when tid<256

#define GRU_ISSUE(s, k0) do { \
    uint32_t sb = smBase + (uint32_t)(GRU_W_ELEMS + (s) * GRU_STG_ELEMS) * 2; \
    cp16(sb + wlo_so * 2, wlo_rp + (k0)); \
    if (tid < 256) { \
        cp16(sb + (3456u + wlo_so) * 2, hHi + h_go + (k0)); \
        cp16(sb + (5760u + wlo_so) * 2, hLo + h_go + (k0)); \
    } } while (0)

#pragma unroll 1
    for (int t = 0; t < Tt; t++) {
        const bf16* hHi = g_hstate[t & 1][0];
        const bf16* hLo = g_hstate[t & 1][1];

        float acc[4] = {0.f, 0.f, 0.f, 0.f};

        GRU_ISSUE(0, 0);
        CP_COMMIT;
#pragma unroll 1
        for (int c = 0; c < 32; c++) {
            if (c < 31) { GRU_ISSUE((c + 1) & 1, (c + 1) << 6); CP_COMMIT; CP_WAIT1; }
            else { CP_WAIT0; }
            __syncthreads();
            const int st = c & 1;
            const uint16_t* Wl_s = sm + GRU_W_ELEMS + st * GRU_STG_ELEMS;
            const uint16_t* Hh_s = Wl_s + 3456;
            const uint16_t* Hl_s = Wl_s + 5760;
            const int k0 = c << 6;
#pragma unroll
            for (int ks = 0; ks < 4; ks++) {
                const int kb = ks * 16;
                uint32_t ah[4], al[4], bh[2], bl[2];
                ldsm4f(ah, Hh_s, GLD, mt * 16, kb, lane);
                ldsm4f(al, Hl_s, GLD, mt * 16, kb, lane);
                ldsm2f(bh, sm,   WLD, nt * 8, k0 + kb, lane);
                ldsm2f(bl, Wl_s, GLD, nt * 8, kb, lane);
                MMA4(acc, ah, bh[0], bh[1]);
                MMA4(acc, ah, bl[0], bl[1]);
                MMA4(acc, al, bh[0], bh[1]);
            }
            __syncthreads();
        }

        // scatter hp into (aliased) smem: hp[gate_row][batch], stride 33
        float* hp = (float*)(sm + GRU_W_ELEMS);
        {
            int col = nt * 8 + cc2, row = mt * 16 + gr;
            hp[col * 33 + row]           = acc[0];
            hp[(col + 1) * 33 + row]     = acc[1];
            hp[col * 33 + row + 8]       = acc[2];
            hp[(col + 1) * 33 + row + 8] = acc[3];
        }
        __syncthreads();

        const float* HTprev = g_HT[t & 1];
        float* HTnext = g_HT[(t & 1) ^ 1];
        bf16* nHi = g_hstate[(t & 1) ^ 1][0];
        bf16* nLo = g_hstate[(t & 1) ^ 1][1];
#pragma unroll
        for (int i = 0; i < 2; i++) {
            int oi = tid + i * 384;
            if (oi < 512) {
                int b = oi & 31, jj = oi >> 5, j = jbase + jj;
                size_t xoff = ((size_t)b * Tt + t) * G3 + j;
                float xr = g_XP[xoff];
                float xz = g_XP[xoff + Hh];
                float xn = g_XP[xoff + 2 * Hh];
                float hr = hp[jj * 33 + b]        + bhh[j];
                float hz = hp[(16 + jj) * 33 + b] + bhh[Hh + j];
                float hn = hp[(32 + jj) * 33 + b] + bhh[2 * Hh + j];
                float r = sigmoidf_(xr + hr);
                float z = sigmoidf_(xz + hz);
                float n = tanhf(xn + r * hn);
                float hprev = HTprev[j * 32 + b];
                float hnew = (1.0f - z) * n + z * hprev;
                HTnext[j * 32 + b] = hnew;
                uint16_t hh, hl;
                split_bf16(hnew, hh, hl);
                nHi[(size_t)b * Hh + j] = __ushort_as_bfloat16(hh);
                nLo[(size_t)b * Hh + j] = __ushort_as_bfloat16(hl);
                g_Hb[0][((size_t)b * Tt + t) * Hh + j] = __ushort_as_bfloat16(hh);
                g_Hb[1][((size_t)b * Tt + t) * Hh + j] = __ushort_as_bfloat16(hl);
            }
        }

        // global barrier between steps
        __threadfence();
        __syncthreads();
        if (tid == 0) {
            unsigned a = atomicAdd(&g_count, 1u);
            if (a == 127u) {
                g_count = 0u;
                __threadfence();
                atomicAdd(&g_gen, 1u);
            } else {
                while (*(volatile unsigned*)&g_gen <= (unsigned)t) __nanosleep(32);
            }
        }
        __syncthreads();
    }
}

// ---------------- heads ------------------------------------------------------
__global__ __launch_bounds__(128)
void heads_kernel(const int* __restrict__ labels,
                  const float* __restrict__ W4, const float* __restrict__ b4,
                  const float* __restrict__ W5, const float* __restrict__ b5,
                  const float* __restrict__ W6, const float* __restrict__ b6,
                  const float* __restrict__ Wp, const float* __restrict__ bp,
                  float* __restrict__ out) {
    const int bt   = blockIdx.x;
    const int b    = bt >> 7;
    const int t    = bt & 127;
    const int lane = threadIdx.x & 31;
    const int w    = threadIdx.x >> 5;
    const int lab  = labels[b];
    const float4* s4 = (const float4*)(g_S + (size_t)bt * PEN);

    for (int hh = w; hh < 7; hh += 4) {
        const float* Wrow;
        float bias;
        if (hh == 0)      { Wrow = W4 + (size_t)lab * PEN; bias = b4[lab]; }
        else if (hh == 1) { Wrow = W5 + (size_t)lab * PEN; bias = b5[lab]; }
        else if (hh == 2) { Wrow = W6 + (size_t)lab * PEN; bias = b6[lab]; }
        else {
            int p = hh - 3;
            Wrow = Wp + ((size_t)p * Cc + lab) * PEN;
            bias = bp[p * Cc + lab];
        }
        const float4* w4 = (const float4*)Wrow;
        float acc = 0.0f;
        for (int q = lane; q < PEN / 4; q += 32) {
            float4 sv = s4[q];
            float4 wv = w4[q];
            acc += sv.x * wv.x + sv.y * wv.y + sv.z * wv.z + sv.w * wv.w;
        }
#pragma unroll
        for (int off = 16; off > 0; off >>= 1)
            acc += __shfl_down_sync(0xffffffffu, acc, off);
        if (lane == 0) {
            float v = acc + bias;
            if (hh < 3) out[hh * BT + bt] = v;
            else {
                int p = hh - 3;
                out[3 * BT + ((size_t)p * Bb + b) * Tt + t] = 1.0f / (1.0f + expf(-v));
            }
        }
    }
}

// ---------------- launch -----------------------------------------------------
extern "C" void kernel_launch(void* const* d_in, const int* in_sizes, int n_in,
                              void* d_out, int out_size) {
    const float* x    = (const float*)d_in[0];
    const int*   lab  = (const int*)  d_in[1];
    const float* W1   = (const float*)d_in[2];
    const float* b1   = (const float*)d_in[3];
    const float* W2   = (const float*)d_in[4];
    const float* b2   = (const float*)d_in[5];
    const float* W_ih = (const float*)d_in[6];
    const float* b_ih = (const float*)d_in[7];
    const float* W_hh = (const float*)d_in[8];
    const float* b_hh = (const float*)d_in[9];
    const float* W3   = (const float*)d_in[10];
    const float* b3   = (const float*)d_in[11];
    const float* W4   = (const float*)d_in[12];
    const float* b4   = (const float*)d_in[13];
    const float* W5   = (const float*)d_in[14];
    const float* b5   = (const float*)d_in[15];
    const float* W6   = (const float*)d_in[16];
    const float* b6   = (const float*)d_in[17];
    const float* Wp   = (const float*)d_in[18];
    const float* bp   = (const float*)d_in[19];
    float* out = (float*)d_out;

    float *XP, *S;
    bf16 *xb[2], *W1b[2], *W2b[2], *Wihb[2], *Whhb[2], *W3b[2], *A1b[2], *A2b[2], *Hbp[2];
    cudaGetSymbolAddress((void**)&XP, g_XP);
    cudaGetSymbolAddress((void**)&S,  g_S);
    {
        char* p;
        cudaGetSymbolAddress((void**)&p, g_xb);
        xb[0] = (bf16*)p; xb[1] = xb[0] + BT * DIN;
        cudaGetSymbolAddress((void**)&p, g_W1b);
        W1b[0] = (bf16*)p; W1b[1] = W1b[0] + H1 * DIN;
        cudaGetSymbolAddress((void**)&p, g_W2b);
        W2b[0] = (bf16*)p; W2b[1] = W2b[0] + (size_t)Hh * H1;
        cudaGetSymbolAddress((void**)&p, g_Wihb);
        Wihb[0] = (bf16*)p; Wihb[1] = Wihb[0] + (size_t)G3 * Hh;
        cudaGetSymbolAddress((void**)&p, g_Whhb);
        Whhb[0] = (bf16*)p; Whhb[1] = Whhb[0] + (size_t)G3 * Hh;
        cudaGetSymbolAddress((void**)&p, g_W3b);
        W3b[0] = (bf16*)p; W3b[1] = W3b[0] + (size_t)PEN * Hh;
        cudaGetSymbolAddress((void**)&p, g_A1b);
        A1b[0] = (bf16*)p; A1b[1] = A1b[0] + (size_t)BT * H1;
        cudaGetSymbolAddress((void**)&p, g_A2b);
        A2b[0] = (bf16*)p; A2b[1] = A2b[0] + (size_t)BT * Hh;
        cudaGetSymbolAddress((void**)&p, g_Hb);
        Hbp[0] = (bf16*)p; Hbp[1] = Hbp[0] + (size_t)BT * Hh;
    }

    cudaFuncSetAttribute(gemm3p<true,  true >, cudaFuncAttributeMaxDynamicSharedMemorySize, GEMM_SMEM);
    cudaFuncSetAttribute(gemm3p<false, false>, cudaFuncAttributeMaxDynamicSharedMemorySize, GEMM_SMEM);
    cudaFuncSetAttribute(gemm3p<true,  false>, cudaFuncAttributeMaxDynamicSharedMemorySize, GEMM_SMEM);
    cudaFuncSetAttribute(gru_persist, cudaFuncAttributeMaxDynamicSharedMemorySize, GRU_SMEM);

    init_kernel<<<256, 256>>>(out, out_size);

    // conversions (once per launch)
    convert_split_k<<<(BT * DIN) / (256 * 8), 256>>>(x, xb[0], xb[1]);
    convert_split_k<<<(H1 * DIN) / (256 * 8), 256>>>(W1, W1b[0], W1b[1]);
    convert_split_k<<<(Hh * H1) / (256 * 8), 256>>>(W2, W2b[0], W2b[1]);
    convert_split_k<<<(G3 * Hh) / (256 * 8), 256>>>(W_ih, Wihb[0], Wihb[1]);
    convert_split_k<<<(G3 * Hh) / (256 * 8), 256>>>(W_hh, Whhb[0], Whhb[1]);
    convert_split_k<<<(PEN * Hh) / (256 * 8), 256>>>(W3, W3b[0], W3b[1]);

    // layer1: relu(x @ W1^T + b1) -> A1 (bf16 hi/lo)
    gemm3p<true, true><<<dim3(H1 / 128, BT / 128), 256, GEMM_SMEM>>>(
        xb[0], xb[1], W1b[0], W1b[1], b1, nullptr, A1b[0], A1b[1], BT, H1, DIN);
    // layer2: relu(A1 @ W2^T + b2) -> A2 (bf16 hi/lo)
    gemm3p<true, true><<<dim3(Hh / 128, BT / 128), 256, GEMM_SMEM>>>(
        A1b[0], A1b[1], W2b[0], W2b[1], b2, nullptr, A2b[0], A2b[1], BT, Hh, H1);
    // xp: A2 @ W_ih^T + b_ih -> XP (fp32)
    gemm3p<false, false><<<dim3(G3 / 128, BT / 128), 256, GEMM_SMEM>>>(
        A2b[0], A2b[1], Wihb[0], Wihb[1], b_ih, XP, nullptr, nullptr, BT, G3, Hh);
    // GRU: single persistent kernel, 128 steps
    gru_persist<<<128, 384, GRU_SMEM>>>(b_hh);
    // layer3: relu(H @ W3^T + b3) -> S (fp32)
    gemm3p<true, false><<<dim3(PEN / 128, BT / 128), 256, GEMM_SMEM>>>(
        Hbp[0], Hbp[1], W3b[0], W3b[1], b3, S, nullptr, nullptr, BT, PEN, Hh);
    // heads
    heads_kernel<<<BT, 128>>>(lab, W4, b4, W5, b5, W6, b6, Wp, bp, out);
}

// round 8
// speedup vs baseline: 2.2925x; 1.0181x over previous
#include <cuda_runtime.h>
#include <cuda_bf16.h>
#include <math.h>
#include <stdint.h>

#define Bb   32
#define Tt   128
#define BT   4096
#define DIN  32
#define H1   1024
#define Hh   2048
#define G3   6144
#define PEN  1024
#define Cc   64
#define Pp   4

typedef __nv_bfloat16 bf16;

// ---------------- device globals (no allocation) -----------------------------
__device__ __align__(16) float g_XP[(size_t)BT * G3];
__device__ __align__(16) float g_S [BT * PEN];
__device__ __align__(16) float g_HT[2][Hh * Bb];
__device__ __align__(16) bf16  g_xb  [2][BT * DIN];
__device__ __align__(16) bf16  g_W1b [2][H1 * DIN];
__device__ __align__(16) bf16  g_W2b [2][(size_t)Hh * H1];
__device__ __align__(16) bf16  g_Wihb[2][(size_t)G3 * Hh];
__device__ __align__(16) bf16  g_Whhb[2][(size_t)G3 * Hh];
__device__ __align__(16) bf16  g_W3b [2][(size_t)PEN * Hh];
__device__ __align__(16) bf16  g_A1b [2][(size_t)BT * H1];
__device__ __align__(16) bf16  g_A2b [2][(size_t)BT * Hh];
__device__ __align__(16) bf16  g_Hb  [2][(size_t)BT * Hh];
// packed W_hh-lo: [block(128)][chunk(32)][48 rows][64] swizzled, 6KB chunks
__device__ __align__(16) bf16  g_WloPk[(size_t)128 * 32 * 48 * 64];
// packed h state: [buf][hi/lo][chunk(32)][b(32)][64] swizzled, 4KB chunks
__device__ __align__(16) bf16  g_hpk[2][2][32 * 32 * 64];
__device__ unsigned g_gen;
__device__ unsigned g_count;

// ---------------- helpers ----------------------------------------------------
__device__ __forceinline__ void split_bf16(float a, uint16_t& h, uint16_t& l) {
    __nv_bfloat16 bh = __float2bfloat16_rn(a);
    float r = a - __bfloat162float(bh);
    __nv_bfloat16 bl = __float2bfloat16_rn(r);
    h = __bfloat16_as_ushort(bh);
    l = __bfloat16_as_ushort(bl);
}
__device__ __forceinline__ uint32_t pack16(uint16_t a, uint16_t b) {
    return (uint32_t)a | ((uint32_t)b << 16);
}
__device__ __forceinline__ void cp16(uint32_t sa, const void* g) {
    asm volatile("cp.async.cg.shared.global [%0], [%1], 16;" :: "r"(sa), "l"(g));
}
#define CP_COMMIT asm volatile("cp.async.commit_group;")
#define CP_WAIT1  asm volatile("cp.async.wait_group 1;")
#define CP_WAIT0  asm volatile("cp.async.wait_group 0;")

// ldmatrix from padded row-major smem (LD in elems)
__device__ __forceinline__ void ldsm4f(uint32_t* r, const uint16_t* arr, int LD,
                                       int rowBase, int col, int lane) {
    int q = lane >> 3, rr = lane & 7;
    const uint16_t* p = arr + (rowBase + rr + ((q & 1) << 3)) * LD + col + ((q >> 1) << 3);
    uint32_t a = (uint32_t)__cvta_generic_to_shared(p);
    asm volatile("ldmatrix.sync.aligned.m8n8.x4.shared.b16 {%0,%1,%2,%3}, [%4];"
        : "=r"(r[0]), "=r"(r[1]), "=r"(r[2]), "=r"(r[3]) : "r"(a));
}
__device__ __forceinline__ void ldsm2f(uint32_t* r, const uint16_t* arr, int LD,
                                       int rowBase, int col, int lane) {
    int l = lane & 15; int q = l >> 3, rr = l & 7;
    const uint16_t* p = arr + (rowBase + rr) * LD + col + (q << 3);
    uint32_t a = (uint32_t)__cvta_generic_to_shared(p);
    asm volatile("ldmatrix.sync.aligned.m8n8.x2.shared.b16 {%0,%1}, [%2];"
        : "=r"(r[0]), "=r"(r[1]) : "r"(a));
}
// ldmatrix from packed 128B-pitch tiles with 16B-unit swizzle u^(row&7)
__device__ __forceinline__ void ldsm4_sw(uint32_t* r, const uint16_t* base,
                                         int rowBase, int kb, int lane) {
    int q = lane >> 3, rr = lane & 7;
    int row = rowBase + rr + ((q & 1) << 3);
    int u = (kb >> 3) + (q >> 1);
    uint32_t a = (uint32_t)__cvta_generic_to_shared(base) + row * 128 + ((u ^ (row & 7)) << 4);
    asm volatile("ldmatrix.sync.aligned.m8n8.x4.shared.b16 {%0,%1,%2,%3}, [%4];"
        : "=r"(r[0]), "=r"(r[1]), "=r"(r[2]), "=r"(r[3]) : "r"(a));
}
__device__ __forceinline__ void ldsm2_sw(uint32_t* r, const uint16_t* base,
                                         int rowBase, int kb, int lane) {
    int l = lane & 15; int q = l >> 3, rr = l & 7;
    int row = rowBase + rr;
    int u = (kb >> 3) + q;
    uint32_t a = (uint32_t)__cvta_generic_to_shared(base) + row * 128 + ((u ^ (row & 7)) << 4);
    asm volatile("ldmatrix.sync.aligned.m8n8.x2.shared.b16 {%0,%1}, [%2];"
        : "=r"(r[0]), "=r"(r[1]) : "r"(a));
}
#define MMA4(c, af, b0, b1) \
    asm volatile("mma.sync.aligned.m16n8k16.row.col.f32.bf16.bf16.f32 " \
        "{%0,%1,%2,%3},{%4,%5,%6,%7},{%8,%9},{%0,%1,%2,%3};" \
        : "+f"((c)[0]),"+f"((c)[1]),"+f"((c)[2]),"+f"((c)[3]) \
        : "r"((af)[0]),"r"((af)[1]),"r"((af)[2]),"r"((af)[3]),"r"(b0),"r"(b1))

__device__ __forceinline__ float sigmoidf_(float x) { return 1.0f / (1.0f + expf(-x)); }

// ---------------- init: zero h state, barrier, AND output tail ---------------
__global__ void init_kernel(float* __restrict__ out, int out_size) {
    int i = blockIdx.x * blockDim.x + threadIdx.x;   // 65536 threads
    if (i < Hh * Bb) {
        g_HT[0][i] = 0.0f;
        g_hpk[0][0][2 * i]     = __ushort_as_bfloat16((uint16_t)0);
        g_hpk[0][0][2 * i + 1] = __ushort_as_bfloat16((uint16_t)0);
        g_hpk[0][1][2 * i]     = __ushort_as_bfloat16((uint16_t)0);
        g_hpk[0][1][2 * i + 1] = __ushort_as_bfloat16((uint16_t)0);
    }
    int tail = 28672 + i;          // heads write [0, 28672); zero the rest
    if (tail < out_size) out[tail] = 0.0f;
    if (i == 0) { g_gen = 0u; g_count = 0u; }
}

// ---------------- fp32 -> split bf16 hi/lo -----------------------------------
__global__ __launch_bounds__(256)
void convert_split_k(const float* __restrict__ src, bf16* __restrict__ hi,
                     bf16* __restrict__ lo) {
    size_t base = ((size_t)blockIdx.x * 256 + threadIdx.x) * 8;
    float4 v0 = *(const float4*)(src + base);
    float4 v1 = *(const float4*)(src + base + 4);
    uint16_t h[8], l[8];
    split_bf16(v0.x,h[0],l[0]); split_bf16(v0.y,h[1],l[1]);
    split_bf16(v0.z,h[2],l[2]); split_bf16(v0.w,h[3],l[3]);
    split_bf16(v1.x,h[4],l[4]); split_bf16(v1.y,h[5],l[5]);
    split_bf16(v1.z,h[6],l[6]); split_bf16(v1.w,h[7],l[7]);
    uint4 ph, pl;
    ph.x = pack16(h[0],h[1]); ph.y = pack16(h[2],h[3]);
    ph.z = pack16(h[4],h[5]); ph.w = pack16(h[6],h[7]);
    pl.x = pack16(l[0],l[1]); pl.y = pack16(l[2],l[3]);
    pl.z = pack16(l[4],l[5]); pl.w = pack16(l[6],l[7]);
    *(uint4*)(hi + base) = ph;
    *(uint4*)(lo + base) = pl;
}

// ---------------- pack W_hh-lo into per-(block,chunk) contiguous tiles -------
// dst tile: [48][64] per chunk, row pitch 128B, 16B-unit swizzle u^(r&7).
__global__ __launch_bounds__(256)
void pack_wlo() {
    int gid = blockIdx.x * 256 + threadIdx.x;        // 1,572,864 units of 16B
    int bk   = gid / 12288;
    int rem  = gid - bk * 12288;
    int c    = rem / 384;
    int rem2 = rem - c * 384;
    int r    = rem2 >> 3;
    int pu   = rem2 & 7;
    int u    = pu ^ (r & 7);
    int g = r >> 4, jj = r & 15;
    const uint4* src = (const uint4*)(g_Whhb[1] +
        ((size_t)(g * Hh + bk * 16 + jj)) * Hh + c * 64 + u * 8);
    uint4* dst = (uint4*)(g_WloPk +
        ((size_t)((bk * 32 + c) * 48 + r)) * 64 + pu * 8);
    *dst = *src;
}

// ---------------- 3-pass split-bf16 tensor-core GEMM (unchanged) -------------
#define SLD 40
#define GEMM_SMEM (2 * 4 * 128 * SLD * 2)   // 81920 B

template<bool RELU, bool BF16OUT>
__global__ __launch_bounds__(256)
void gemm3p(const bf16* __restrict__ Ah, const bf16* __restrict__ Al,
            const bf16* __restrict__ Wh, const bf16* __restrict__ Wl,
            const float* __restrict__ bias,
            float* __restrict__ outF, bf16* __restrict__ outH, bf16* __restrict__ outL,
            int M, int N, int K) {
    extern __shared__ char raw[];
    uint16_t* sm = (uint16_t*)raw;
    const int tid = threadIdx.x, lane = tid & 31, wid = tid >> 5;
    const int wm = (wid & 3) * 32, wn = (wid >> 2) * 64;
    const int n0 = blockIdx.x * 128, m0 = blockIdx.y * 128;
    const int gr = lane >> 2, c2 = (lane & 3) * 2;
    const int row0 = tid >> 2, seg = (tid & 3) << 3;
    const uint32_t smBase = (uint32_t)__cvta_generic_to_shared(sm);

    const bf16* gAh = Ah + (size_t)m0 * K;
    const bf16* gAl = Al + (size_t)m0 * K;
    const bf16* gWh = Wh + (size_t)n0 * K;
    const bf16* gWl = Wl + (size_t)n0 * K;

    float acc[2][8][4];
#pragma unroll
    for (int i = 0; i < 2; i++)
#pragma unroll
        for (int j = 0; j < 8; j++)
#pragma unroll
            for (int e = 0; e < 4; e++) acc[i][j][e] = 0.0f;

#define GISS(ptr, aidx, rep, s, k0) \
    cp16(smBase + (uint32_t)((((s)*4+(aidx))*(128*SLD)) + (row0 + (rep)*64)*SLD + seg)*2, \
         (ptr) + (size_t)(row0 + (rep)*64) * K + (k0) + seg)
#define GEMM_ISSUE(s, k0) do { \
    GISS(gAh, 0, 0, s, k0); GISS(gAh, 0, 1, s, k0); \
    GISS(gAl, 1, 0, s, k0); GISS(gAl, 1, 1, s, k0); \
    GISS(gWh, 2, 0, s, k0); GISS(gWh, 2, 1, s, k0); \
    GISS(gWl, 3, 0, s, k0); GISS(gWl, 3, 1, s, k0); } while (0)

    const int nch = K >> 5;
    GEMM_ISSUE(0, 0);
    CP_COMMIT;
#pragma unroll 1
    for (int c = 0; c < nch; c++) {
        if (c + 1 < nch) { GEMM_ISSUE((c + 1) & 1, (c + 1) << 5); CP_COMMIT; CP_WAIT1; }
        else { CP_WAIT0; }
        __syncthreads();
        const int st = c & 1;
        const uint16_t* Ah_s = sm + (st * 4 + 0) * (128 * SLD);
        const uint16_t* Al_s = sm + (st * 4 + 1) * (128 * SLD);
        const uint16_t* Wh_s = sm + (st * 4 + 2) * (128 * SLD);
        const uint16_t* Wl_s = sm + (st * 4 + 3) * (128 * SLD);
#pragma unroll
        for (int ks = 0; ks < 2; ks++) {
            const int kb = ks * 16;
            uint32_t ahf[2][4], alf[2][4];
#pragma unroll
            for (int mt = 0; mt < 2; mt++) {
                ldsm4f(ahf[mt], Ah_s, SLD, wm + mt * 16, kb, lane);
                ldsm4f(alf[mt], Al_s, SLD, wm + mt * 16, kb, lane);
            }
#pragma unroll
            for (int p = 0; p < 4; p++) {
                uint32_t bh[4], bl[4];
                ldsm4f(bh, Wh_s, SLD, wn + p * 16, kb, lane);
                ldsm4f(bl, Wl_s, SLD, wn + p * 16, kb, lane);
#pragma unroll
                for (int e = 0; e < 2; e++) {
                    const int nt = p * 2 + e;
#pragma unroll
                    for (int mt = 0; mt < 2; mt++) {
                        MMA4(acc[mt][nt], ahf[mt], bh[e], bh[2 + e]);
                        MMA4(acc[mt][nt], ahf[mt], bl[e], bl[2 + e]);
                        MMA4(acc[mt][nt], alf[mt], bh[e], bh[2 + e]);
                    }
                }
            }
        }
        __syncthreads();
    }

#pragma unroll
    for (int mt = 0; mt < 2; mt++) {
        const int r = m0 + wm + mt * 16 + gr;
#pragma unroll
        for (int nt = 0; nt < 8; nt++) {
            const int cb = n0 + wn + nt * 8 + c2;
            float bx = bias[cb], by = bias[cb + 1];
            float v0 = acc[mt][nt][0] + bx;
            float v1 = acc[mt][nt][1] + by;
            float v2 = acc[mt][nt][2] + bx;
            float v3 = acc[mt][nt][3] + by;
            if (RELU) {
                v0 = fmaxf(v0, 0.0f); v1 = fmaxf(v1, 0.0f);
                v2 = fmaxf(v2, 0.0f); v3 = fmaxf(v3, 0.0f);
            }
            if (BF16OUT) {
                uint16_t h0,l0,h1,l1;
                split_bf16(v0,h0,l0); split_bf16(v1,h1,l1);
                *(uint32_t*)(outH + (size_t)r * N + cb) = pack16(h0,h1);
                *(uint32_t*)(outL + (size_t)r * N + cb) = pack16(l0,l1);
                split_bf16(v2,h0,l0); split_bf16(v3,h1,l1);
                *(uint32_t*)(outH + (size_t)(r + 8) * N + cb) = pack16(h0,h1);
                *(uint32_t*)(outL + (size_t)(r + 8) * N + cb) = pack16(l0,l1);
            } else {
                *(float2*)(outF + (size_t)r * N + cb)       = make_float2(v0, v1);
                *(float2*)(outF + (size_t)(r + 8) * N + cb) = make_float2(v2, v3);
            }
        }
    }
}

// ---------------- persistent GRU with bulk-TMA staging -----------------------
// 128 blocks x 384 threads. W_hh-hi slice resident in smem; per chunk a single
// thread issues 3 bulk TMA copies (W_lo 6KB, hHi 4KB, hLo 4KB) -> mbarrier.
#define WLD 2056
#define GRU_W_ELEMS (48 * WLD)            // 98688 elems (197376 B)
#define GRU_STG_ELEMS 7168                // 3072 Wlo + 2048 hHi + 2048 hLo
#define GRU_STG_BYTES (GRU_STG_ELEMS * 2) // 14336
#define GRU_SMEM ((GRU_W_ELEMS + 2 * GRU_STG_ELEMS) * 2)   // 226048 B

__global__ __launch_bounds__(384)
void gru_persist(const float* __restrict__ bhh) {
    extern __shared__ char raw[];
    uint16_t* sm = (uint16_t*)raw;
    __shared__ __align__(8) uint64_t s_mbar[2];
    const int tid = threadIdx.x, lane = tid & 31, wid = tid >> 5;
    const int nt = wid % 6, mt = wid / 6;
    const int jbase = blockIdx.x * 16;
    const int gr = lane >> 2, cc2 = (lane & 3) * 2;
    const uint32_t smBase = (uint32_t)__cvta_generic_to_shared(sm);
    const uint32_t stgBase = smBase + GRU_W_ELEMS * 2;
    const uint32_t mbarBase = (uint32_t)__cvta_generic_to_shared(s_mbar);

    // prologue: W_hh hi slice resident (48 rows x 2048, padded LD)
    for (int i = tid; i < 48 * 256; i += 384) {
        int row = i >> 8;
        int s8  = (i & 255) << 3;
        int g = row >> 4, jj = row & 15;
        *(uint4*)(sm + row * WLD + s8) =
            *(const uint4*)(g_Whhb[0] + (size_t)(g * Hh + jbase + jj) * Hh + s8);
    }
    if (tid == 0) {
        asm volatile("mbarrier.init.shared.b64 [%0], 1;" :: "r"(mbarBase) : "memory");
        asm volatile("mbarrier.init.shared.b64 [%0], 1;" :: "r"(mbarBase + 8) : "memory");
    }
    __syncthreads();

    const bf16* wloB = g_WloPk + (size_t)blockIdx.x * 32 * 3072;
    int ph[2] = {0, 0};

    auto issue = [&](int c, const bf16* hHi, const bf16* hLo) {
        int s = c & 1;
        uint32_t bar = mbarBase + s * 8;
        uint32_t db  = stgBase + (uint32_t)s * GRU_STG_BYTES;
        asm volatile("mbarrier.arrive.expect_tx.shared.b64 _, [%0], %1;"
            :: "r"(bar), "r"((uint32_t)GRU_STG_BYTES) : "memory");
        asm volatile("cp.async.bulk.shared::cta.global.mbarrier::complete_tx::bytes [%0], [%1], %2, [%3];"
            :: "r"(db), "l"((const void*)(wloB + (size_t)c * 3072)), "r"(6144u), "r"(bar) : "memory");
        asm volatile("cp.async.bulk.shared::cta.global.mbarrier::complete_tx::bytes [%0], [%1], %2, [%3];"
            :: "r"(db + 6144u), "l"((const void*)(hHi + (size_t)c * 2048)), "r"(4096u), "r"(bar) : "memory");
        asm volatile("cp.async.bulk.shared::cta.global.mbarrier::complete_tx::bytes [%0], [%1], %2, [%3];"
            :: "r"(db + 10240u), "l"((const void*)(hLo + (size_t)c * 2048)), "r"(4096u), "r"(bar) : "memory");
    };
    auto wait_stage = [&](int s) {
        uint32_t bar = mbarBase + s * 8;
        uint32_t p = (uint32_t)ph[s];
        uint32_t done;
        do {
            asm volatile("{\n\t.reg .pred P;\n\t"
                "mbarrier.try_wait.parity.shared.b64 P, [%1], %2, 0x989680;\n\t"
                "selp.b32 %0, 1, 0, P;\n\t}"
                : "=r"(done) : "r"(bar), "r"(p) : "memory");
        } while (!done);
        ph[s] ^= 1;
    };

#pragma unroll 1
    for (int t = 0; t < Tt; t++) {
        const bf16* hHi = g_hpk[t & 1][0];
        const bf16* hLo = g_hpk[t & 1][1];

        if (tid == 0) { issue(0, hHi, hLo); issue(1, hHi, hLo); }

        float acc[4] = {0.f, 0.f, 0.f, 0.f};
#pragma unroll 1
        for (int c = 0; c < 32; c++) {
            const int s = c & 1;
            wait_stage(s);
            const uint16_t* Wl_s = sm + GRU_W_ELEMS + s * GRU_STG_ELEMS;
            const uint16_t* Hh_s = Wl_s + 3072;
            const uint16_t* Hl_s = Hh_s + 2048;
            const int k0 = c << 6;
#pragma unroll
            for (int ks = 0; ks < 4; ks++) {
                const int kb = ks * 16;
                uint32_t ah[4], al[4], bh[2], bl[2];
                ldsm4_sw(ah, Hh_s, mt * 16, kb, lane);
                ldsm4_sw(al, Hl_s, mt * 16, kb, lane);
                ldsm2f(bh, sm, WLD, nt * 8, k0 + kb, lane);   // resident W_hi
                ldsm2_sw(bl, Wl_s, nt * 8, kb, lane);
                MMA4(acc, ah, bh[0], bh[1]);
                MMA4(acc, ah, bl[0], bl[1]);
                MMA4(acc, al, bh[0], bh[1]);
            }
            __syncthreads();
            if (tid == 0 && c + 2 < 32) issue(c + 2, hHi, hLo);
        }

        // scatter accum into (stage-area) smem: hp[gate_row][batch], stride 33
        float* hp = (float*)(sm + GRU_W_ELEMS);
        {
            int col = nt * 8 + cc2, row = mt * 16 + gr;
            hp[col * 33 + row]           = acc[0];
            hp[(col + 1) * 33 + row]     = acc[1];
            hp[col * 33 + row + 8]       = acc[2];
            hp[(col + 1) * 33 + row + 8] = acc[3];
        }
        __syncthreads();

        const float* HTprev = g_HT[t & 1];
        float* HTnext = g_HT[(t & 1) ^ 1];
        bf16* nHi = g_hpk[(t & 1) ^ 1][0];
        bf16* nLo = g_hpk[(t & 1) ^ 1][1];
#pragma unroll
        for (int i = 0; i < 2; i++) {
            int oi = tid + i * 384;
            if (oi < 512) {
                int b = oi & 31, jj = oi >> 5, j = jbase + jj;
                size_t xoff = ((size_t)b * Tt + t) * G3 + j;
                float xr = g_XP[xoff];
                float xz = g_XP[xoff + Hh];
                float xn = g_XP[xoff + 2 * Hh];
                float hr = hp[jj * 33 + b]        + bhh[j];
                float hz = hp[(16 + jj) * 33 + b] + bhh[Hh + j];
                float hn = hp[(32 + jj) * 33 + b] + bhh[2 * Hh + j];
                float r = sigmoidf_(xr + hr);
                float z = sigmoidf_(xz + hz);
                float n = tanhf(xn + r * hn);
                float hprev = HTprev[j * 32 + b];
                float hnew = (1.0f - z) * n + z * hprev;
                HTnext[j * 32 + b] = hnew;
                uint16_t hh, hl;
                split_bf16(hnew, hh, hl);
                // packed+swizzled h write: chunk=j>>6, row=b, col=j&63
                int ck = j >> 6, k = j & 63, u = k >> 3;
                size_t e = ((size_t)((ck << 5) + b) << 6) +
                           (size_t)(((u ^ (b & 7)) << 3) + (k & 7));
                nHi[e] = __ushort_as_bfloat16(hh);
                nLo[e] = __ushort_as_bfloat16(hl);
                g_Hb[0][((size_t)b * Tt + t) * Hh + j] = __ushort_as_bfloat16(hh);
                g_Hb[1][((size_t)b * Tt + t) * Hh + j] = __ushort_as_bfloat16(hl);
            }
        }

        // global barrier between steps (order STG h-writes before TMA reads)
        asm volatile("fence.proxy.async;" ::: "memory");
        __threadfence();
        __syncthreads();
        if (tid == 0) {
            unsigned a = atomicAdd(&g_count, 1u);
            if (a == 127u) {
                g_count = 0u;
                __threadfence();
                atomicAdd(&g_gen, 1u);
            } else {
                while (*(volatile unsigned*)&g_gen <= (unsigned)t) __nanosleep(32);
            }
        }
        __syncthreads();
    }
}

// ---------------- heads ------------------------------------------------------
__global__ __launch_bounds__(128)
void heads_kernel(const int* __restrict__ labels,
                  const float* __restrict__ W4, const float* __restrict__ b4,
                  const float* __restrict__ W5, const float* __restrict__ b5,
                  const float* __restrict__ W6, const float* __restrict__ b6,
                  const float* __restrict__ Wp, const float* __restrict__ bp,
                  float* __restrict__ out) {
    const int bt   = blockIdx.x;
    const int b    = bt >> 7;
    const int t    = bt & 127;
    const int lane = threadIdx.x & 31;
    const int w    = threadIdx.x >> 5;
    const int lab  = labels[b];
    const float4* s4 = (const float4*)(g_S + (size_t)bt * PEN);

    for (int hh = w; hh < 7; hh += 4) {
        const float* Wrow;
        float bias;
        if (hh == 0)      { Wrow = W4 + (size_t)lab * PEN; bias = b4[lab]; }
        else if (hh == 1) { Wrow = W5 + (size_t)lab * PEN; bias = b5[lab]; }
        else if (hh == 2) { Wrow = W6 + (size_t)lab * PEN; bias = b6[lab]; }
        else {
            int p = hh - 3;
            Wrow = Wp + ((size_t)p * Cc + lab) * PEN;
            bias = bp[p * Cc + lab];
        }
        const float4* w4 = (const float4*)Wrow;
        float acc = 0.0f;
        for (int q = lane; q < PEN / 4; q += 32) {
            float4 sv = s4[q];
            float4 wv = w4[q];
            acc += sv.x * wv.x + sv.y * wv.y + sv.z * wv.z + sv.w * wv.w;
        }
#pragma unroll
        for (int off = 16; off > 0; off >>= 1)
            acc += __shfl_down_sync(0xffffffffu, acc, off);
        if (lane == 0) {
            float v = acc + bias;
            if (hh < 3) out[hh * BT + bt] = v;
            else {
                int p = hh - 3;
                out[3 * BT + ((size_t)p * Bb + b) * Tt + t] = 1.0f / (1.0f + expf(-v));
            }
        }
    }
}

// ---------------- launch -----------------------------------------------------
extern "C" void kernel_launch(void* const* d_in, const int* in_sizes, int n_in,
                              void* d_out, int out_size) {
    const float* x    = (const float*)d_in[0];
    const int*   lab  = (const int*)  d_in[1];
    const float* W1   = (const float*)d_in[2];
    const float* b1   = (const float*)d_in[3];
    const float* W2   = (const float*)d_in[4];
    const float* b2   = (const float*)d_in[5];
    const float* W_ih = (const float*)d_in[6];
    const float* b_ih = (const float*)d_in[7];
    const float* W_hh = (const float*)d_in[8];
    const float* b_hh = (const float*)d_in[9];
    const float* W3   = (const float*)d_in[10];
    const float* b3   = (const float*)d_in[11];
    const float* W4   = (const float*)d_in[12];
    const float* b4   = (const float*)d_in[13];
    const float* W5   = (const float*)d_in[14];
    const float* b5   = (const float*)d_in[15];
    const float* W6   = (const float*)d_in[16];
    const float* b6   = (const float*)d_in[17];
    const float* Wp   = (const float*)d_in[18];
    const float* bp   = (const float*)d_in[19];
    float* out = (float*)d_out;

    float *XP, *S;
    bf16 *xb[2], *W1b[2], *W2b[2], *Wihb[2], *Whhb[2], *W3b[2], *A1b[2], *A2b[2], *Hbp[2];
    cudaGetSymbolAddress((void**)&XP, g_XP);
    cudaGetSymbolAddress((void**)&S,  g_S);
    {
        char* p;
        cudaGetSymbolAddress((void**)&p, g_xb);
        xb[0] = (bf16*)p; xb[1] = xb[0] + BT * DIN;
        cudaGetSymbolAddress((void**)&p, g_W1b);
        W1b[0] = (bf16*)p; W1b[1] = W1b[0] + H1 * DIN;
        cudaGetSymbolAddress((void**)&p, g_W2b);
        W2b[0] = (bf16*)p; W2b[1] = W2b[0] + (size_t)Hh * H1;
        cudaGetSymbolAddress((void**)&p, g_Wihb);
        Wihb[0] = (bf16*)p; Wihb[1] = Wihb[0] + (size_t)G3 * Hh;
        cudaGetSymbolAddress((void**)&p, g_Whhb);
        Whhb[0] = (bf16*)p; Whhb[1] = Whhb[0] + (size_t)G3 * Hh;
        cudaGetSymbolAddress((void**)&p, g_W3b);
        W3b[0] = (bf16*)p; W3b[1] = W3b[0] + (size_t)PEN * Hh;
        cudaGetSymbolAddress((void**)&p, g_A1b);
        A1b[0] = (bf16*)p; A1b[1] = A1b[0] + (size_t)BT * H1;
        cudaGetSymbolAddress((void**)&p, g_A2b);
        A2b[0] = (bf16*)p; A2b[1] = A2b[0] + (size_t)BT * Hh;
        cudaGetSymbolAddress((void**)&p, g_Hb);
        Hbp[0] = (bf16*)p; Hbp[1] = Hbp[0] + (size_t)BT * Hh;
    }

    cudaFuncSetAttribute(gemm3p<true,  true >, cudaFuncAttributeMaxDynamicSharedMemorySize, GEMM_SMEM);
    cudaFuncSetAttribute(gemm3p<false, false>, cudaFuncAttributeMaxDynamicSharedMemorySize, GEMM_SMEM);
    cudaFuncSetAttribute(gemm3p<true,  false>, cudaFuncAttributeMaxDynamicSharedMemorySize, GEMM_SMEM);
    cudaFuncSetAttribute(gru_persist, cudaFuncAttributeMaxDynamicSharedMemorySize, GRU_SMEM);

    init_kernel<<<256, 256>>>(out, out_size);

    // conversions (once per launch)
    convert_split_k<<<(BT * DIN) / (256 * 8), 256>>>(x, xb[0], xb[1]);
    convert_split_k<<<(H1 * DIN) / (256 * 8), 256>>>(W1, W1b[0], W1b[1]);
    convert_split_k<<<(Hh * H1) / (256 * 8), 256>>>(W2, W2b[0], W2b[1]);
    convert_split_k<<<(G3 * Hh) / (256 * 8), 256>>>(W_ih, Wihb[0], Wihb[1]);
    convert_split_k<<<(G3 * Hh) / (256 * 8), 256>>>(W_hh, Whhb[0], Whhb[1]);
    convert_split_k<<<(PEN * Hh) / (256 * 8), 256>>>(W3, W3b[0], W3b[1]);
    pack_wlo<<<6144, 256>>>();

    // layer1: relu(x @ W1^T + b1) -> A1 (bf16 hi/lo)
    gemm3p<true, true><<<dim3(H1 / 128, BT / 128), 256, GEMM_SMEM>>>(
        xb[0], xb[1], W1b[0], W1b[1], b1, nullptr, A1b[0], A1b[1], BT, H1, DIN);
    // layer2: relu(A1 @ W2^T + b2) -> A2 (bf16 hi/lo)
    gemm3p<true, true><<<dim3(Hh / 128, BT / 128), 256, GEMM_SMEM>>>(
        A1b[0], A1b[1], W2b[0], W2b[1], b2, nullptr, A2b[0], A2b[1], BT, Hh, H1);
    // xp: A2 @ W_ih^T + b_ih -> XP (fp32)
    gemm3p<false, false><<<dim3(G3 / 128, BT / 128), 256, GEMM_SMEM>>>(
        A2b[0], A2b[1], Wihb[0], Wihb[1], b_ih, XP, nullptr, nullptr, BT, G3, Hh);
    // GRU: single persistent kernel, 128 steps, bulk-TMA staging
    gru_persist<<<128, 384, GRU_SMEM>>>(b_hh);
    // layer3: relu(H @ W3^T + b3) -> S (fp32)
    gemm3p<true, false><<<dim3(PEN / 128, BT / 128), 256, GEMM_SMEM>>>(
        Hbp[0], Hbp[1], W3b[0], W3b[1], b3, S, nullptr, nullptr, BT, PEN, Hh);
    // heads
    heads_kernel<<<BT, 128>>>(lab, W4, b4, W5, b5, W6, b6, Wp, bp, out);
}